// round 12
// baseline (speedup 1.0000x reference)
#include <cuda_runtime.h>
#include <cuda_fp16.h>
#include <cstdint>

// Problem constants: B=8192, T=2048, H=5, input dim 1.
#define MAX_B 8192
#define MAX_T 2048
#define HID 5

typedef unsigned long long ull;

// Packed x: xP[t/8][b][8] -> 32B per sequence per 8 steps, coalesced.
__device__ float g_xP[(size_t)MAX_T * MAX_B];

__device__ __forceinline__ float fast_tanh(float x) {
    float r;
    asm("tanh.approx.f32 %0, %1;" : "=f"(r) : "f"(x));
    return r;
}
// Packed half2 tanh: one MUFU op, two tanhs.
__device__ __forceinline__ uint32_t tanh_h2(uint32_t x) {
    uint32_t r;
    asm("tanh.approx.f16x2 %0, %1;" : "=r"(r) : "r"(x));
    return r;
}
// Pack two f32 into f16x2: lo = b, hi = a.
__device__ __forceinline__ uint32_t cvt_h2(float hi, float lo) {
    uint32_t r;
    asm("cvt.rn.f16x2.f32 %0, %1, %2;" : "=r"(r) : "f"(hi), "f"(lo));
    return r;
}
__device__ __forceinline__ ull pk2(float lo, float hi) {
    ull r;
    asm("mov.b64 %0, {%1, %2};" : "=l"(r) : "f"(lo), "f"(hi));
    return r;
}
__device__ __forceinline__ void upk2(ull v, float& lo, float& hi) {
    asm("mov.b64 {%0, %1}, %2;" : "=f"(lo), "=f"(hi) : "l"(v));
}
// Packed fp32x2 FMA (sm_100+): one instruction = 2 fp32 FMAs.
__device__ __forceinline__ ull fma2(ull a, ull b, ull c) {
    ull r;
    asm("fma.rn.f32x2 %0, %1, %2, %3;" : "=l"(r) : "l"(a), "l"(b), "l"(c));
    return r;
}

// ---------------- pack: x[B,T] -> xP[T/8][B][8] ----------------
__global__ void pack_kernel(const float* __restrict__ x, int B, int T) {
    const int nblk = T / 8;
    int idx = blockIdx.x * blockDim.x + threadIdx.x;   // over B * nblk
    if (idx >= B * nblk) return;
    int b = idx / nblk;
    int k = idx - b * nblk;
    const float4* src = reinterpret_cast<const float4*>(x + (size_t)b * T + (size_t)k * 8);
    float4 u = src[0];
    float4 v = src[1];
    float4* dst = reinterpret_cast<float4*>(g_xP + ((size_t)k * B + b) * 8);
    dst[0] = u;
    dst[1] = v;
}

// ---------------- LSTM: 5 lanes/seq, lane = hidden unit, f16x2 tanh -------
// Warp = 6 groups of 5 lanes (lanes 30,31 junk-compute a clamped seq).
// Lane (group g, role j) owns unit j completely. Gate tanhs evaluated as two
// packed tanh.approx.f16x2 ops (i,f) and (g,o); cell tanh stays f32 MUFU.
// MUFU warp-instrs/step: 3 (was 5) -> tanh-pipe floor 144 cyc/SMSP-step.
// 1536 warps = 128 blocks x 384 threads -> 3 warps/SMSP on 512 SMSPs.
__global__ void __launch_bounds__(384, 1) lstm_kernel(
    const float* __restrict__ W_ih,   // [20,1]
    const float* __restrict__ W_hh,   // [20,5]
    const float* __restrict__ b_ih,   // [20]
    const float* __restrict__ b_hh,   // [20]
    const float* __restrict__ W_fc,   // [1,5]
    const float* __restrict__ b_fc,   // [1]
    float* __restrict__ out,          // [B,1]
    int B, int T)
{
    const int lane = threadIdx.x & 31;
    const int warpGlobal = (blockIdx.x * (blockDim.x >> 5)) + (threadIdx.x >> 5);
    const int grp  = lane / 5;                 // 0..6 (grp 6 = 2 leftover lanes)
    const int role = lane - grp * 5;           // 0..4 (unit index)
    const int base = grp * 5;                  // first lane of the group

    const int seqRaw = warpGlobal * 6 + grp;   // 6 real groups per warp
    const bool valid = (grp < 6) && (seqRaw < B);
    const int s = valid ? seqRaw : (B - 1);    // clamp: junk lanes do real math

    // Own unit u = role. Rows (PyTorch order): i=u, f=5+u, g=10+u, o=15+u.
    // sigmoid(z) = 0.5*tanh(z/2)+0.5 -> fold 0.5 into i,f,o rows; g row x1.
    ull wif, wgo, bif, bgo, whhif[HID], whhgo[HID];
    {
        const int ri = role, rf = 5 + role, rg = 10 + role, ro = 15 + role;
        wif = pk2(W_ih[ri] * 0.5f, W_ih[rf] * 0.5f);
        wgo = pk2(W_ih[rg],        W_ih[ro] * 0.5f);
        bif = pk2((b_ih[ri] + b_hh[ri]) * 0.5f, (b_ih[rf] + b_hh[rf]) * 0.5f);
        bgo = pk2((b_ih[rg] + b_hh[rg]),        (b_ih[ro] + b_hh[ro]) * 0.5f);
        #pragma unroll
        for (int k = 0; k < HID; k++) {
            whhif[k] = pk2(W_hh[ri * HID + k] * 0.5f, W_hh[rf * HID + k] * 0.5f);
            whhgo[k] = pk2(W_hh[rg * HID + k],        W_hh[ro * HID + k] * 0.5f);
        }
    }

    float h[HID];
    #pragma unroll
    for (int j = 0; j < HID; j++) h[j] = 0.0f;
    float cq = 0.0f;

    const int nblk = T / 8;
    const float4* xp0 = reinterpret_cast<const float4*>(g_xP);

    // prime first x block (5 lanes of a group read the same 32B -> broadcast)
    float4 xu = xp0[((size_t)0 * B + s) * 2 + 0];
    float4 xv = xp0[((size_t)0 * B + s) * 2 + 1];

    for (int tb = 0; tb < nblk; tb++) {
        const int tn = (tb + 1 < nblk) ? (tb + 1) : tb;
        const float4 un = xp0[((size_t)tn * B + s) * 2 + 0];
        const float4 vn = xp0[((size_t)tn * B + s) * 2 + 1];

        const float xs[8] = {xu.x, xu.y, xu.z, xu.w, xv.x, xv.y, xv.z, xv.w};

        #pragma unroll
        for (int kk = 0; kk < 8; kk++) {
            const float xval = xs[kk];
            const ull x2 = pk2(xval, xval);

            // z rows for the own unit, two partial chains to cut depth.
            ull zifA = fma2(x2, wif, bif);
            ull zgoA = fma2(x2, wgo, bgo);
            {
                const ull h0 = pk2(h[0], h[0]);
                const ull h1 = pk2(h[1], h[1]);
                const ull h2 = pk2(h[2], h[2]);
                zifA = fma2(h0, whhif[0], zifA);
                zgoA = fma2(h0, whhgo[0], zgoA);
                zifA = fma2(h1, whhif[1], zifA);
                zgoA = fma2(h1, whhgo[1], zgoA);
                zifA = fma2(h2, whhif[2], zifA);
                zgoA = fma2(h2, whhgo[2], zgoA);
            }
            {
                const ull h3 = pk2(h[3], h[3]);
                const ull h4 = pk2(h[4], h[4]);
                ull zifB = fma2(h3, whhif[3], pk2(0.0f, 0.0f));
                ull zgoB = fma2(h3, whhgo[3], pk2(0.0f, 0.0f));
                zifB = fma2(h4, whhif[4], zifB);
                zgoB = fma2(h4, whhgo[4], zgoB);
                const ull ONE2 = pk2(1.0f, 1.0f);
                zifA = fma2(zifB, ONE2, zifA);
                zgoA = fma2(zgoB, ONE2, zgoA);
            }

            float zi, zf, zg, zo;
            upk2(zifA, zi, zf);
            upk2(zgoA, zg, zo);

            // packed gate tanhs: (i,f) and (g,o) in f16x2; cell tanh stays f32
            const uint32_t tif = tanh_h2(cvt_h2(zf, zi));   // lo=tanh(zi), hi=tanh(zf)
            const uint32_t tgo = tanh_h2(cvt_h2(zo, zg));   // lo=tanh(zg), hi=tanh(zo)
            const __half2 hif = *reinterpret_cast<const __half2*>(&tif);
            const __half2 hgo = *reinterpret_cast<const __half2*>(&tgo);
            const float ti = __low2float(hif), tf = __high2float(hif);
            const float tg = __low2float(hgo), to = __high2float(hgo);

            const float ig = fmaf(0.5f, ti, 0.5f);
            const float fg = fmaf(0.5f, tf, 0.5f);
            const float og = fmaf(0.5f, to, 0.5f);
            cq = fmaf(fg, cq, ig * tg);
            const float hq = og * fast_tanh(cq);

            // broadcast the 5 unit h-values within the group (independent shfls)
            h[0] = __shfl_sync(0xffffffffu, hq, base + 0);
            h[1] = __shfl_sync(0xffffffffu, hq, base + 1);
            h[2] = __shfl_sync(0xffffffffu, hq, base + 2);
            h[3] = __shfl_sync(0xffffffffu, hq, base + 3);
            h[4] = __shfl_sync(0xffffffffu, hq, base + 4);
        }

        xu = un; xv = vn;
    }

    // relu(h) @ W_fc^T + b_fc  (role-0 lane of each valid group writes)
    if (valid && role == 0) {
        float y = b_fc[0];
        #pragma unroll
        for (int j = 0; j < HID; j++) y = fmaf(fmaxf(h[j], 0.0f), W_fc[j], y);
        out[s] = y;
    }
}

extern "C" void kernel_launch(void* const* d_in, const int* in_sizes, int n_in,
                              void* d_out, int out_size) {
    const float* x    = (const float*)d_in[0];
    const float* W_ih = (const float*)d_in[1];
    const float* W_hh = (const float*)d_in[2];
    const float* b_ih = (const float*)d_in[3];
    const float* b_hh = (const float*)d_in[4];
    const float* W_fc = (const float*)d_in[5];
    const float* b_fc = (const float*)d_in[6];
    float* out = (float*)d_out;

    const int B = out_size;              // 8192
    const int T = in_sizes[0] / B;       // 2048

    const int npack = B * (T / 8);
    pack_kernel<<<(npack + 255) / 256, 256>>>(x, B, T);

    // 5 lanes/seq, 6 seqs/warp: 1536 warps = 128 blocks x 384 threads
    // -> 12 warps/SM on 128 SMs = exactly 3 warps per SMSP.
    const int threads = 384;
    const int blocks = 128;
    lstm_kernel<<<blocks, threads>>>(W_ih, W_hh, b_ih, b_hh, W_fc, b_fc, out, B, T);
}

// round 13
// speedup vs baseline: 1.0950x; 1.0950x over previous
#include <cuda_runtime.h>
#include <cstdint>

// Problem constants: B=8192, T=2048, H=5, input dim 1.
#define MAX_B 8192
#define MAX_T 2048
#define HID 5

typedef unsigned long long ull;

// Packed x: xP[t/8][b][8] -> 32B per sequence per 8 steps, coalesced.
__device__ float g_xP[(size_t)MAX_T * MAX_B];

__device__ __forceinline__ float fast_tanh(float x) {
    float r;
    asm("tanh.approx.f32 %0, %1;" : "=f"(r) : "f"(x));
    return r;
}
__device__ __forceinline__ ull pk2(float lo, float hi) {
    ull r;
    asm("mov.b64 %0, {%1, %2};" : "=l"(r) : "f"(lo), "f"(hi));
    return r;
}
__device__ __forceinline__ void upk2(ull v, float& lo, float& hi) {
    asm("mov.b64 {%0, %1}, %2;" : "=f"(lo), "=f"(hi) : "l"(v));
}
// Packed fp32x2 FMA (sm_100+): one instruction = 2 fp32 FMAs.
__device__ __forceinline__ ull fma2(ull a, ull b, ull c) {
    ull r;
    asm("fma.rn.f32x2 %0, %1, %2, %3;" : "=l"(r) : "l"(a), "l"(b), "l"(c));
    return r;
}

// ---------------- pack: x[B,T] -> xP[T/8][B][8] ----------------
__global__ void pack_kernel(const float* __restrict__ x, int B, int T) {
    const int nblk = T / 8;
    int idx = blockIdx.x * blockDim.x + threadIdx.x;   // over B * nblk
    if (idx >= B * nblk) return;
    int b = idx / nblk;
    int k = idx - b * nblk;
    const float4* src = reinterpret_cast<const float4*>(x + (size_t)b * T + (size_t)k * 8);
    float4 u = src[0];
    float4 v = src[1];
    float4* dst = reinterpret_cast<float4*>(g_xP + ((size_t)k * B + b) * 8);
    dst[0] = u;
    dst[1] = v;
}

// ---------------- LSTM: 5 lanes/seq, lane = hidden unit, f32 tanh ---------
// Warp = 6 groups of 5 lanes (lanes 30,31 junk-compute a clamped seq).
// Lane (group g, role j) owns unit j completely: c_j/h_j update lane-local.
// Only communication: 5-value h broadcast (5 independent SHFL.IDX).
// Grid = S blocks (S = actual SM count, queried at launch), W warps/block
// with W = ceil(1366/S) -> one block per SM, ~2.25-2.5 warps/SMSP; MUFU
// floor per SMSP-step drops from 240 (128-SM config) to 180-200 cyc.
__global__ void __launch_bounds__(384, 1) lstm_kernel(
    const float* __restrict__ W_ih,   // [20,1]
    const float* __restrict__ W_hh,   // [20,5]
    const float* __restrict__ b_ih,   // [20]
    const float* __restrict__ b_hh,   // [20]
    const float* __restrict__ W_fc,   // [1,5]
    const float* __restrict__ b_fc,   // [1]
    float* __restrict__ out,          // [B,1]
    int B, int T)
{
    const int lane = threadIdx.x & 31;
    const int warpGlobal = (blockIdx.x * (blockDim.x >> 5)) + (threadIdx.x >> 5);
    const int grp  = lane / 5;                 // 0..6 (grp 6 = 2 leftover lanes)
    const int role = lane - grp * 5;           // 0..4 (unit index)
    const int base = grp * 5;                  // first lane of the group

    const int seqRaw = warpGlobal * 6 + grp;   // 6 real groups per warp
    const bool valid = (grp < 6) && (seqRaw < B);
    const int s = valid ? seqRaw : (B - 1);    // clamp: junk lanes do real math

    // Own unit u = role. Rows (PyTorch order): i=u, f=5+u, g=10+u, o=15+u.
    // sigmoid(z) = 0.5*tanh(z/2)+0.5 -> fold 0.5 into i,f,o rows; g row x1.
    ull wif, wgo, bif, bgo, whhif[HID], whhgo[HID];
    {
        const int ri = role, rf = 5 + role, rg = 10 + role, ro = 15 + role;
        wif = pk2(W_ih[ri] * 0.5f, W_ih[rf] * 0.5f);
        wgo = pk2(W_ih[rg],        W_ih[ro] * 0.5f);
        bif = pk2((b_ih[ri] + b_hh[ri]) * 0.5f, (b_ih[rf] + b_hh[rf]) * 0.5f);
        bgo = pk2((b_ih[rg] + b_hh[rg]),        (b_ih[ro] + b_hh[ro]) * 0.5f);
        #pragma unroll
        for (int k = 0; k < HID; k++) {
            whhif[k] = pk2(W_hh[ri * HID + k] * 0.5f, W_hh[rf * HID + k] * 0.5f);
            whhgo[k] = pk2(W_hh[rg * HID + k],        W_hh[ro * HID + k] * 0.5f);
        }
    }

    float h[HID];
    #pragma unroll
    for (int j = 0; j < HID; j++) h[j] = 0.0f;
    float cq = 0.0f;

    const int nblk = T / 8;
    const float4* xp0 = reinterpret_cast<const float4*>(g_xP);

    // prime first x block (5 lanes of a group read the same 32B -> broadcast)
    float4 xu = xp0[((size_t)0 * B + s) * 2 + 0];
    float4 xv = xp0[((size_t)0 * B + s) * 2 + 1];

    for (int tb = 0; tb < nblk; tb++) {
        const int tn = (tb + 1 < nblk) ? (tb + 1) : tb;
        const float4 un = xp0[((size_t)tn * B + s) * 2 + 0];
        const float4 vn = xp0[((size_t)tn * B + s) * 2 + 1];

        const float xs[8] = {xu.x, xu.y, xu.z, xu.w, xv.x, xv.y, xv.z, xv.w};

        #pragma unroll
        for (int kk = 0; kk < 8; kk++) {
            const float xval = xs[kk];
            const ull x2 = pk2(xval, xval);

            // z rows for the own unit, two partial chains to cut depth.
            ull zifA = fma2(x2, wif, bif);
            ull zgoA = fma2(x2, wgo, bgo);
            {
                const ull h0 = pk2(h[0], h[0]);
                const ull h1 = pk2(h[1], h[1]);
                const ull h2 = pk2(h[2], h[2]);
                zifA = fma2(h0, whhif[0], zifA);
                zgoA = fma2(h0, whhgo[0], zgoA);
                zifA = fma2(h1, whhif[1], zifA);
                zgoA = fma2(h1, whhgo[1], zgoA);
                zifA = fma2(h2, whhif[2], zifA);
                zgoA = fma2(h2, whhgo[2], zgoA);
            }
            {
                const ull h3 = pk2(h[3], h[3]);
                const ull h4 = pk2(h[4], h[4]);
                ull zifB = fma2(h3, whhif[3], pk2(0.0f, 0.0f));
                ull zgoB = fma2(h3, whhgo[3], pk2(0.0f, 0.0f));
                zifB = fma2(h4, whhif[4], zifB);
                zgoB = fma2(h4, whhgo[4], zgoB);
                const ull ONE2 = pk2(1.0f, 1.0f);
                zifA = fma2(zifB, ONE2, zifA);
                zgoA = fma2(zgoB, ONE2, zgoA);
            }

            float zi, zf, zg, zo;
            upk2(zifA, zi, zf);
            upk2(zgoA, zg, zo);

            const float ig = fmaf(0.5f, fast_tanh(zi), 0.5f);
            const float fg = fmaf(0.5f, fast_tanh(zf), 0.5f);
            const float gg = fast_tanh(zg);
            const float og = fmaf(0.5f, fast_tanh(zo), 0.5f);
            cq = fmaf(fg, cq, ig * gg);
            const float hq = og * fast_tanh(cq);

            // broadcast the 5 unit h-values within the group (independent shfls)
            h[0] = __shfl_sync(0xffffffffu, hq, base + 0);
            h[1] = __shfl_sync(0xffffffffu, hq, base + 1);
            h[2] = __shfl_sync(0xffffffffu, hq, base + 2);
            h[3] = __shfl_sync(0xffffffffu, hq, base + 3);
            h[4] = __shfl_sync(0xffffffffu, hq, base + 4);
        }

        xu = un; xv = vn;
    }

    // relu(h) @ W_fc^T + b_fc  (role-0 lane of each valid group writes)
    if (valid && role == 0) {
        float y = b_fc[0];
        #pragma unroll
        for (int j = 0; j < HID; j++) y = fmaf(fmaxf(h[j], 0.0f), W_fc[j], y);
        out[s] = y;
    }
}

extern "C" void kernel_launch(void* const* d_in, const int* in_sizes, int n_in,
                              void* d_out, int out_size) {
    const float* x    = (const float*)d_in[0];
    const float* W_ih = (const float*)d_in[1];
    const float* W_hh = (const float*)d_in[2];
    const float* b_ih = (const float*)d_in[3];
    const float* b_hh = (const float*)d_in[4];
    const float* W_fc = (const float*)d_in[5];
    const float* b_fc = (const float*)d_in[6];
    float* out = (float*)d_out;

    const int B = out_size;              // 8192
    const int T = in_sizes[0] / B;       // 2048

    const int npack = B * (T / 8);
    pack_kernel<<<(npack + 255) / 256, 256>>>(x, B, T);

    // Spread across ALL SMs: one block per SM (grid == SM count is load-
    // bearing: any SM with 2 blocks would carry 2x MUFU load and gate the
    // wall). W = ceil(warps_needed / S) warps per block.
    int S = 0;
    cudaDeviceGetAttribute(&S, cudaDevAttrMultiProcessorCount, 0);
    if (S <= 0) S = 128;                 // defensive fallback
    const int warpsNeeded = (B + 5) / 6; // 1366 for B=8192
    int W = (warpsNeeded + S - 1) / S;   // 9 @ S=152, 10 @ S=148
    if (W > 12) W = 12;                  // cap at 384 threads (launch_bounds)
    const int threads = W * 32;
    const int blocks = S;
    lstm_kernel<<<blocks, threads>>>(W_ih, W_hh, b_ih, b_hh, W_fc, b_fc, out, B, T);
}